// round 5
// baseline (speedup 1.0000x reference)
#include <cuda_runtime.h>
#include <math_constants.h>

// Problem constants
#define BB 4
#define NN 4096
#define FF 15
#define AA 24
#define AFN 14
#define HID 10
#define KSEL 204
#define SCALE 0.31622776601683794f   // 1/sqrt(10)
#define RPB 4                        // rows per attn block (warp per row)
#define FULL 0xffffffffu

typedef unsigned long long ull;

// ---------------- scratch (device globals; no allocation allowed) ----------------
__device__ float g_q[BB * NN * HID];          // [b][n][d]
__device__ float g_kT[BB * HID * NN];         // [b][d][n]  (transposed, fp32)
__device__ float g_v[BB * NN * HID];          // [b][n][d]
__device__ float g_logits[BB * NN * 2];       // [b][n][c]

// ---------------- helpers ----------------
__device__ __forceinline__ unsigned orderf(float f) {
    unsigned u = __float_as_uint(f);
    return (u & 0x80000000u) ? ~u : (u | 0x80000000u);
}
__device__ __forceinline__ float unorderf(unsigned u) {
    return (u & 0x80000000u) ? __uint_as_float(u ^ 0x80000000u)
                             : __uint_as_float(~u);
}

// ---------------- Kernel 1: conv features (warp per seq) + QKV projection ----------------
// filters in concat order: H = {2,2,2,3,3,3,4,4,4,5,5,6,6,7}, 14 filters, 56 weights per i
__global__ __launch_bounds__(256) void conv_qkv_kernel(
    const float* __restrict__ x,
    const float* __restrict__ cw2, const float* __restrict__ cb2,
    const float* __restrict__ cw3, const float* __restrict__ cb3,
    const float* __restrict__ cw4, const float* __restrict__ cb4,
    const float* __restrict__ cw5, const float* __restrict__ cb5,
    const float* __restrict__ cw6, const float* __restrict__ cb6,
    const float* __restrict__ cw7, const float* __restrict__ cb7,
    const float* __restrict__ wq, const float* __restrict__ bq,
    const float* __restrict__ wk, const float* __restrict__ bk,
    const float* __restrict__ wv, const float* __restrict__ bv) {
    __shared__ __align__(16) float wsm[FF * 56];   // [i][packed 56]
    __shared__ float bsm[AFN];
    __shared__ float xsm[8][FF * 32];              // per-seq x rows padded to 32

    const int tid = threadIdx.x;
    const int lane = tid & 31;
    const int w = tid >> 5;
    const int seq = blockIdx.x * 8 + w;

    // ---- stage weights repacked to [i][f-packed] ----
    for (int e = tid; e < FF * 56; e += 256) {
        int i = e / 56, r = e % 56;
        int f, dt;
        if (r < 6)       { f = r >> 1;            dt = r & 1; }
        else if (r < 15) { f = 3 + (r - 6) / 3;   dt = (r - 6) % 3; }
        else if (r < 27) { f = 6 + (r - 15) / 4;  dt = (r - 15) & 3; }
        else if (r < 37) { f = 9 + (r - 27) / 5;  dt = (r - 27) % 5; }
        else if (r < 49) { f = 11 + (r - 37) / 6; dt = (r - 37) % 6; }
        else             { f = 13;                dt = r - 49; }
        const float* src; int H, fl;
        if (f < 3)       { src = cw2; H = 2; fl = f; }
        else if (f < 6)  { src = cw3; H = 3; fl = f - 3; }
        else if (f < 9)  { src = cw4; H = 4; fl = f - 6; }
        else if (f < 11) { src = cw5; H = 5; fl = f - 9; }
        else if (f < 13) { src = cw6; H = 6; fl = f - 11; }
        else             { src = cw7; H = 7; fl = 0; }
        wsm[i * 56 + r] = src[(fl * FF + i) * H + dt];
    }
    if (tid < AFN) {
        float bv_;
        if (tid < 3)       bv_ = cb2[tid];
        else if (tid < 6)  bv_ = cb3[tid - 3];
        else if (tid < 9)  bv_ = cb4[tid - 6];
        else if (tid < 11) bv_ = cb5[tid - 9];
        else if (tid < 13) bv_ = cb6[tid - 11];
        else               bv_ = cb7[0];
        bsm[tid] = bv_;
    }

    // ---- stage this warp's sequence x (360 floats) ----
    const float* xg = x + (size_t)seq * (FF * AA);
    for (int idx = lane; idx < FF * AA; idx += 32) {
        int i = idx / AA, c = idx % AA;
        xsm[w][i * 32 + c] = xg[idx];
    }
    for (int p = lane; p < FF * 8; p += 32) {       // zero pad cols 24..31
        int i = p / 8, c = 24 + (p & 7);
        xsm[w][i * 32 + c] = 0.f;
    }
    __syncthreads();

    // ---- conv: lane t computes all 14 filter outputs at position t ----
    const int Hs[14] = {2,2,2,3,3,3,4,4,4,5,5,6,6,7};
    const int FO[14] = {0,2,4,6,9,12,15,19,23,27,32,37,43,49};
    float y[AFN];
#pragma unroll
    for (int f = 0; f < AFN; f++) y[f] = 0.f;
    const int t = lane;
    if (t < AA) {
#pragma unroll
        for (int i = 0; i < FF; i++) {
            float xw[7];
#pragma unroll
            for (int dt = 0; dt < 7; dt++) xw[dt] = xsm[w][i * 32 + t + dt];
            float W[56];
            const float4* wp = (const float4*)(wsm + i * 56);
#pragma unroll
            for (int q4 = 0; q4 < 14; q4++) ((float4*)W)[q4] = wp[q4];
#pragma unroll
            for (int f = 0; f < AFN; f++)
#pragma unroll
                for (int dt = 0; dt < Hs[f]; dt++)
                    y[f] += xw[dt] * W[FO[f] + dt];
        }
    }
    // ---- max over positions (valid t only) + bias + relu; all lanes get result ----
    float feat[AFN];
#pragma unroll
    for (int f = 0; f < AFN; f++) {
        const int T = AA - Hs[f] + 1;
        float v = (t < T) ? y[f] : -CUDART_INF_F;
#pragma unroll
        for (int off = 16; off > 0; off >>= 1)
            v = fmaxf(v, __shfl_xor_sync(FULL, v, off));
        feat[f] = fmaxf(v + bsm[f], 0.f);
    }

    // ---- QKV projections: lane o < 30 computes one output ----
    if (lane < 30) {
        int which = lane / 10, oo = lane % 10;
        const float* W; const float* Bv;
        if (which == 0)      { W = wq; Bv = bq; }
        else if (which == 1) { W = wk; Bv = bk; }
        else                 { W = wv; Bv = bv; }
        float acc = Bv[oo];
#pragma unroll
        for (int i = 0; i < AFN; i++) acc += feat[i] * W[oo * AFN + i];
        int b = seq >> 12, n = seq & 4095;
        if (which == 0)      g_q[(b * NN + n) * HID + oo] = acc;
        else if (which == 1) g_kT[(b * HID + oo) * NN + n] = acc;
        else                 g_v[(b * NN + n) * HID + oo] = acc;
    }
}

// ---------------- Kernel 2: scores + per-warp row selection pipeline ----------------
// dynamic smem (bytes): keys RPB*NN*4 = 65536 | scr RPB*2048 (hist 1KB ∪ cand 2KB) | shq RPB*HID*4
#define KEYS_BYTES (RPB * NN * 4)
#define SCR_BYTES  (RPB * 2048)
#define SMEM_TOTAL (KEYS_BYTES + SCR_BYTES + RPB * HID * 4)

// warp-local radix bucket select from 256-bin histogram; updates pref,kneed
__device__ __forceinline__ void radix_select(const unsigned* hrow, int lane,
                                             unsigned& pref, int& kneed) {
    unsigned h8[8];
    int part = 0;
#pragma unroll
    for (int i = 0; i < 8; i++) { h8[i] = hrow[lane * 8 + i]; part += (int)h8[i]; }
    int suff = part;
#pragma unroll
    for (int d2 = 1; d2 < 32; d2 <<= 1) {
        int v = __shfl_down_sync(FULL, suff, d2);
        if (lane + d2 < 32) suff += v;
    }
    int c = suff - part;
    unsigned bsel = 0; int krem = 0; bool found = false;
#pragma unroll
    for (int i = 7; i >= 0; i--) {
        int Cn = c;
        c += (int)h8[i];
        if (!found && c >= kneed && Cn < kneed) {
            bsel = (unsigned)(lane * 8 + i);
            krem = kneed - Cn;
            found = true;
        }
    }
    unsigned fm = __ballot_sync(FULL, found);
    int src = __ffs(fm) - 1;
    pref = (pref << 8) | __shfl_sync(FULL, bsel, src);
    kneed = __shfl_sync(FULL, krem, src);
}

__global__ __launch_bounds__(128) void attn_kernel(
    const float* __restrict__ wattn, const float* __restrict__ battn,
    const float* __restrict__ wmil, const float* __restrict__ bmil,
    float* __restrict__ out) {
    extern __shared__ unsigned char smem_raw[];
    unsigned* keys = (unsigned*)smem_raw;
    float*    shq  = (float*)(smem_raw + KEYS_BYTES + SCR_BYTES);

    const int b = blockIdx.y;
    const int r0 = blockIdx.x * RPB;
    const int tid = threadIdx.x;
    const int lane = tid & 31;
    const int wid = tid >> 5;

    if (tid < RPB * HID) shq[tid] = g_q[((size_t)b * NN + r0) * HID + tid];
    __syncthreads();

    // ---- Phase A: scores for RPB rows -> ordered keys in smem ----
    const float* kt = g_kT + (size_t)b * HID * NN;
#pragma unroll
    for (int g = 0; g < 4; g++) {
        const int jb = g * 1024 + tid * 8;
        float acc[RPB][8];
#pragma unroll
        for (int r = 0; r < RPB; r++)
#pragma unroll
            for (int i = 0; i < 8; i++) acc[r][i] = 0.f;
#pragma unroll
        for (int d = 0; d < HID; d++) {
            float4 k0 = *(const float4*)(kt + d * NN + jb);
            float4 k1 = *(const float4*)(kt + d * NN + jb + 4);
            float kk[8] = {k0.x, k0.y, k0.z, k0.w, k1.x, k1.y, k1.z, k1.w};
#pragma unroll
            for (int r = 0; r < RPB; r++) {
                float qv = shq[r * HID + d];
#pragma unroll
                for (int i = 0; i < 8; i++) acc[r][i] += qv * kk[i];
            }
        }
#pragma unroll
        for (int r = 0; r < RPB; r++) {
            uint4 o0, o1;
            o0.x = orderf(acc[r][0]); o0.y = orderf(acc[r][1]);
            o0.z = orderf(acc[r][2]); o0.w = orderf(acc[r][3]);
            o1.x = orderf(acc[r][4]); o1.y = orderf(acc[r][5]);
            o1.z = orderf(acc[r][6]); o1.w = orderf(acc[r][7]);
            *(uint4*)(keys + r * NN + jb)     = o0;
            *(uint4*)(keys + r * NN + jb + 4) = o1;
        }
    }
    __syncthreads();

    // ---- Phase B: warp `wid` owns row r0+wid, fully warp-local ----
    unsigned* krow = keys + wid * NN;
    unsigned char* scr = smem_raw + KEYS_BYTES + wid * 2048;
    unsigned* hrow = (unsigned*)scr;   // 1KB hist (overlaid with cand)
    ull*      crow = (ull*)scr;        // 2KB candidate buffer

    unsigned pref = 0;
    int kneed = KSEL;

    // pass 1: top byte, warp-aggregated atomics
#pragma unroll
    for (int i = 0; i < 8; i++) hrow[lane * 8 + i] = 0u;
    __syncwarp();
    for (int j = 0; j < 128; j++) {
        unsigned u = krow[j * 32 + lane];
        unsigned bkt = u >> 24;
        unsigned grp = __match_any_sync(FULL, bkt);
        if ((grp & ((1u << lane) - 1u)) == 0u)
            atomicAdd(&hrow[bkt], (unsigned)__popc(grp));
    }
    __syncwarp();
    radix_select(hrow, lane, pref, kneed);
    __syncwarp();

    // pass 2: byte 1 within selected top byte
#pragma unroll
    for (int i = 0; i < 8; i++) hrow[lane * 8 + i] = 0u;
    __syncwarp();
    for (int j = 0; j < 128; j++) {
        unsigned u = krow[j * 32 + lane];
        bool pr = (u >> 24) == pref;
        unsigned act = __ballot_sync(FULL, pr);
        if (pr) {
            unsigned bkt = (u >> 16) & 255u;
            unsigned grp = __match_any_sync(act, bkt);
            if ((grp & ((1u << lane) - 1u)) == 0u)
                atomicAdd(&hrow[bkt], (unsigned)__popc(grp));
        }
    }
    __syncwarp();
    radix_select(hrow, lane, pref, kneed);
    __syncwarp();
    const unsigned pref16 = pref;   // 16-bit prefix of the 204th-largest key

    // compact all keys with (u>>16) >= pref16 (superset of top-204)
#pragma unroll
    for (int e = 0; e < 8; e++) crow[e * 32 + lane] = 0ull;
    __syncwarp();
    unsigned base = 0;
    for (int j = 0; j < 128; j++) {
        unsigned u = krow[j * 32 + lane];
        bool p = (u >> 16) >= pref16;
        unsigned mm = __ballot_sync(FULL, p);
        if (p) {
            unsigned pos = base + __popc(mm & ((1u << lane) - 1u));
            if (pos < 256u)
                crow[pos] = ((ull)u << 32) | (ull)(~(unsigned)(j * 32 + lane));
        }
        base += __popc(mm);
    }
    __syncwarp();

    if (base > 256u) {
        // rare fallback: refine to exact 32-bit threshold via passes 3,4
#pragma unroll
        for (int pass = 2; pass < 4; pass++) {
            const int shift = 24 - 8 * pass;
#pragma unroll
            for (int i = 0; i < 8; i++) hrow[lane * 8 + i] = 0u;
            __syncwarp();
            for (int j = 0; j < 128; j++) {
                unsigned u = krow[j * 32 + lane];
                bool pr = (u >> (shift + 8)) == pref;
                unsigned act = __ballot_sync(FULL, pr);
                if (pr) {
                    unsigned bkt = (u >> shift) & 255u;
                    unsigned grp = __match_any_sync(act, bkt);
                    if ((grp & ((1u << lane) - 1u)) == 0u)
                        atomicAdd(&hrow[bkt], (unsigned)__popc(grp));
                }
            }
            __syncwarp();
            radix_select(hrow, lane, pref, kneed);
            __syncwarp();
        }
        const unsigned T = pref;   // exact key of the 204th largest
#pragma unroll
        for (int e = 0; e < 8; e++) crow[e * 32 + lane] = 0ull;
        __syncwarp();
        base = 0;
        for (int j = 0; j < 128; j++) {
            unsigned u = krow[j * 32 + lane];
            bool p = (u >= T);
            unsigned mm = __ballot_sync(FULL, p);
            if (p) {
                unsigned pos = base + __popc(mm & ((1u << lane) - 1u));
                if (pos < 256u)
                    crow[pos] = ((ull)u << 32) | (ull)(~(unsigned)(j * 32 + lane));
            }
            base += __popc(mm);
        }
        __syncwarp();
    }

    // in-register bitonic sort of 256 elems, 8 per thread; elem index = e*32+lane
    // composite key desc == (value desc, index asc) -> exact lax.top_k order
    ull v8[8];
#pragma unroll
    for (int e = 0; e < 8; e++) v8[e] = crow[e * 32 + lane];

#pragma unroll
    for (int k2 = 2; k2 <= 256; k2 <<= 1) {
#pragma unroll
        for (int j = 128; j > 0; j >>= 1) {
            if (j >= k2) continue;
            if (j >= 32) {
                const int jj = j >> 5;
#pragma unroll
                for (int e = 0; e < 8; e++) {
                    if (e & jj) continue;
                    int ilo = e * 32 + lane;
                    bool up = ((ilo & k2) == 0);
                    ull a = v8[e], bb = v8[e | jj];
                    bool sw = up ? (a < bb) : (a > bb);
                    if (sw) { v8[e] = bb; v8[e | jj] = a; }
                }
            } else {
#pragma unroll
                for (int e = 0; e < 8; e++) {
                    int i = e * 32 + lane;
                    bool up = ((i & k2) == 0);
                    ull other = __shfl_xor_sync(FULL, v8[e], j);
                    bool lower = ((lane & j) == 0);
                    bool takemax = (up == lower);
                    ull mx = (v8[e] > other) ? v8[e] : other;
                    ull mn = (v8[e] > other) ? other : v8[e];
                    v8[e] = takemax ? mx : mn;
                }
            }
        }
    }

    // ---- softmax over top-204 (scaled), exact ref ordering ----
    unsigned topu = __shfl_sync(FULL, (unsigned)(v8[0] >> 32), 0);
    const float smax = unorderf(topu) * SCALE;
    float ex[7];
    float sum = 0.f;
#pragma unroll
    for (int e = 0; e < 7; e++) {
        int rank = e * 32 + lane;
        float sv = unorderf((unsigned)(v8[e] >> 32)) * SCALE;
        float ee = (rank < KSEL) ? __expf(sv - smax) : 0.f;
        ex[e] = ee;
        sum += ee;
    }
#pragma unroll
    for (int off = 16; off > 0; off >>= 1) sum += __shfl_xor_sync(FULL, sum, off);
    const float inv = 1.f / sum;

    // ---- probs out + V gather + context ----
    const float* vbase = g_v + (size_t)b * NN * HID;
    float* orow = out + 8 + ((size_t)(b * NN + r0 + wid)) * KSEL;
    float cd[HID];
#pragma unroll
    for (int d = 0; d < HID; d++) cd[d] = 0.f;
#pragma unroll
    for (int e = 0; e < 7; e++) {
        int rank = e * 32 + lane;
        if (rank < KSEL) {
            float p = ex[e] * inv;
            orow[rank] = p;
            unsigned gidx = ~(unsigned)(v8[e] & 0xffffffffull);
            const float2* vp = (const float2*)(vbase + (size_t)gidx * HID);
            float2 a0 = vp[0], a1 = vp[1], a2 = vp[2], a3 = vp[3], a4 = vp[4];
            cd[0] += p * a0.x; cd[1] += p * a0.y;
            cd[2] += p * a1.x; cd[3] += p * a1.y;
            cd[4] += p * a2.x; cd[5] += p * a2.y;
            cd[6] += p * a3.x; cd[7] += p * a3.y;
            cd[8] += p * a4.x; cd[9] += p * a4.y;
        }
    }
#pragma unroll
    for (int d = 0; d < HID; d++)
#pragma unroll
        for (int off = 16; off > 0; off >>= 1)
            cd[d] += __shfl_xor_sync(FULL, cd[d], off);

    // attn proj (lane < 14 computes one output), then mil proj via reductions
    float sa = 0.f;
    if (lane < AFN) {
        sa = battn[lane];
#pragma unroll
        for (int d = 0; d < HID; d++) sa += cd[d] * wattn[lane * HID + d];
    }
    float t0 = (lane < AFN) ? sa * wmil[lane] : 0.f;
    float t1 = (lane < AFN) ? sa * wmil[AFN + lane] : 0.f;
#pragma unroll
    for (int off = 16; off > 0; off >>= 1) {
        t0 += __shfl_xor_sync(FULL, t0, off);
        t1 += __shfl_xor_sync(FULL, t1, off);
    }
    if (lane == 0) {
        int row = b * NN + r0 + wid;
        g_logits[row * 2 + 0] = t0 + bmil[0];
        g_logits[row * 2 + 1] = t1 + bmil[1];
    }
}

// ---------------- Kernel 3: deterministic pooled reduction ----------------
__global__ __launch_bounds__(256) void pool_kernel(float* __restrict__ out) {
    int w = threadIdx.x >> 5, l = threadIdx.x & 31;
    if (w < 8) {
        int b = w >> 1, c = w & 1;
        float acc = 0.f;
        for (int n = l; n < NN; n += 32) acc += g_logits[(b * NN + n) * 2 + c];
#pragma unroll
        for (int off = 16; off > 0; off >>= 1) acc += __shfl_down_sync(FULL, acc, off);
        if (l == 0) out[b * 2 + c] = acc * (1.0f / (float)NN);
    }
}

// ---------------- launcher ----------------
extern "C" void kernel_launch(void* const* d_in, const int* in_sizes, int n_in,
                              void* d_out, int out_size) {
    const float* x   = (const float*)d_in[0];
    const float* cw2 = (const float*)d_in[1];  const float* cb2 = (const float*)d_in[2];
    const float* cw3 = (const float*)d_in[3];  const float* cb3 = (const float*)d_in[4];
    const float* cw4 = (const float*)d_in[5];  const float* cb4 = (const float*)d_in[6];
    const float* cw5 = (const float*)d_in[7];  const float* cb5 = (const float*)d_in[8];
    const float* cw6 = (const float*)d_in[9];  const float* cb6 = (const float*)d_in[10];
    const float* cw7 = (const float*)d_in[11]; const float* cb7 = (const float*)d_in[12];
    const float* wq  = (const float*)d_in[13]; const float* bq  = (const float*)d_in[14];
    const float* wk  = (const float*)d_in[15]; const float* bk  = (const float*)d_in[16];
    const float* wv  = (const float*)d_in[17]; const float* bv  = (const float*)d_in[18];
    const float* wat = (const float*)d_in[19]; const float* bat = (const float*)d_in[20];
    const float* wm  = (const float*)d_in[21]; const float* bm  = (const float*)d_in[22];
    float* out = (float*)d_out;

    cudaFuncSetAttribute(attn_kernel, cudaFuncAttributeMaxDynamicSharedMemorySize, SMEM_TOTAL);

    conv_qkv_kernel<<<(BB * NN) / 8, 256>>>(x, cw2, cb2, cw3, cb3, cw4, cb4,
                                            cw5, cb5, cw6, cb6, cw7, cb7,
                                            wq, bq, wk, bk, wv, bv);
    attn_kernel<<<dim3(NN / RPB, BB), 128, SMEM_TOTAL>>>(wat, bat, wm, bm, out);
    pool_kernel<<<1, 256>>>(out);
}

// round 6
// speedup vs baseline: 1.1623x; 1.1623x over previous
#include <cuda_runtime.h>
#include <math_constants.h>

// Problem constants
#define BB 4
#define NN 4096
#define FF 15
#define AA 24
#define AFN 14
#define HID 10
#define KSEL 204
#define SCALE 0.31622776601683794f   // 1/sqrt(10)
#define RPB 4                        // rows per attn block (block-cooperative)
#define FULL 0xffffffffu

typedef unsigned long long ull;

// ---------------- scratch (device globals; no allocation allowed) ----------------
__device__ float g_q[BB * NN * HID];          // [b][n][d]
__device__ float g_kT[BB * HID * NN];         // [b][d][n]  (transposed, fp32)
__device__ float g_v[BB * NN * HID];          // [b][n][d]
__device__ float g_logits[BB * NN * 2];       // [b][n][c]

// ---------------- helpers ----------------
__device__ __forceinline__ unsigned orderf(float f) {
    unsigned u = __float_as_uint(f);
    return (u & 0x80000000u) ? ~u : (u | 0x80000000u);
}
__device__ __forceinline__ float unorderf(unsigned u) {
    return (u & 0x80000000u) ? __uint_as_float(u ^ 0x80000000u)
                             : __uint_as_float(~u);
}

// ---------------- Kernel 1: conv features (warp per seq) + QKV projection ----------------
__global__ __launch_bounds__(256) void conv_qkv_kernel(
    const float* __restrict__ x,
    const float* __restrict__ cw2, const float* __restrict__ cb2,
    const float* __restrict__ cw3, const float* __restrict__ cb3,
    const float* __restrict__ cw4, const float* __restrict__ cb4,
    const float* __restrict__ cw5, const float* __restrict__ cb5,
    const float* __restrict__ cw6, const float* __restrict__ cb6,
    const float* __restrict__ cw7, const float* __restrict__ cb7,
    const float* __restrict__ wq, const float* __restrict__ bq,
    const float* __restrict__ wk, const float* __restrict__ bk,
    const float* __restrict__ wv, const float* __restrict__ bv) {
    __shared__ __align__(16) float wsm[FF * 56];   // [i][packed 56]
    __shared__ float bsm[AFN];
    __shared__ float xsm[8][FF * 32];              // per-seq x rows padded to 32

    const int tid = threadIdx.x;
    const int lane = tid & 31;
    const int w = tid >> 5;
    const int seq = blockIdx.x * 8 + w;

    for (int e = tid; e < FF * 56; e += 256) {
        int i = e / 56, r = e % 56;
        int f, dt;
        if (r < 6)       { f = r >> 1;            dt = r & 1; }
        else if (r < 15) { f = 3 + (r - 6) / 3;   dt = (r - 6) % 3; }
        else if (r < 27) { f = 6 + (r - 15) / 4;  dt = (r - 15) & 3; }
        else if (r < 37) { f = 9 + (r - 27) / 5;  dt = (r - 27) % 5; }
        else if (r < 49) { f = 11 + (r - 37) / 6; dt = (r - 37) % 6; }
        else             { f = 13;                dt = r - 49; }
        const float* src; int H, fl;
        if (f < 3)       { src = cw2; H = 2; fl = f; }
        else if (f < 6)  { src = cw3; H = 3; fl = f - 3; }
        else if (f < 9)  { src = cw4; H = 4; fl = f - 6; }
        else if (f < 11) { src = cw5; H = 5; fl = f - 9; }
        else if (f < 13) { src = cw6; H = 6; fl = f - 11; }
        else             { src = cw7; H = 7; fl = 0; }
        wsm[i * 56 + r] = src[(fl * FF + i) * H + dt];
    }
    if (tid < AFN) {
        float bv_;
        if (tid < 3)       bv_ = cb2[tid];
        else if (tid < 6)  bv_ = cb3[tid - 3];
        else if (tid < 9)  bv_ = cb4[tid - 6];
        else if (tid < 11) bv_ = cb5[tid - 9];
        else if (tid < 13) bv_ = cb6[tid - 11];
        else               bv_ = cb7[0];
        bsm[tid] = bv_;
    }

    const float* xg = x + (size_t)seq * (FF * AA);
    for (int idx = lane; idx < FF * AA; idx += 32) {
        int i = idx / AA, c = idx % AA;
        xsm[w][i * 32 + c] = xg[idx];
    }
    for (int p = lane; p < FF * 8; p += 32) {
        int i = p / 8, c = 24 + (p & 7);
        xsm[w][i * 32 + c] = 0.f;
    }
    __syncthreads();

    const int Hs[14] = {2,2,2,3,3,3,4,4,4,5,5,6,6,7};
    const int FO[14] = {0,2,4,6,9,12,15,19,23,27,32,37,43,49};
    float y[AFN];
#pragma unroll
    for (int f = 0; f < AFN; f++) y[f] = 0.f;
    const int t = lane;
    if (t < AA) {
#pragma unroll
        for (int i = 0; i < FF; i++) {
            float xw[7];
#pragma unroll
            for (int dt = 0; dt < 7; dt++) xw[dt] = xsm[w][i * 32 + t + dt];
            float W[56];
            const float4* wp = (const float4*)(wsm + i * 56);
#pragma unroll
            for (int q4 = 0; q4 < 14; q4++) ((float4*)W)[q4] = wp[q4];
#pragma unroll
            for (int f = 0; f < AFN; f++)
#pragma unroll
                for (int dt = 0; dt < Hs[f]; dt++)
                    y[f] += xw[dt] * W[FO[f] + dt];
        }
    }
    float feat[AFN];
#pragma unroll
    for (int f = 0; f < AFN; f++) {
        const int T = AA - Hs[f] + 1;
        float v = (t < T) ? y[f] : -CUDART_INF_F;
#pragma unroll
        for (int off = 16; off > 0; off >>= 1)
            v = fmaxf(v, __shfl_xor_sync(FULL, v, off));
        feat[f] = fmaxf(v + bsm[f], 0.f);
    }

    if (lane < 30) {
        int which = lane / 10, oo = lane % 10;
        const float* W; const float* Bv;
        if (which == 0)      { W = wq; Bv = bq; }
        else if (which == 1) { W = wk; Bv = bk; }
        else                 { W = wv; Bv = bv; }
        float acc = Bv[oo];
#pragma unroll
        for (int i = 0; i < AFN; i++) acc += feat[i] * W[oo * AFN + i];
        int b = seq >> 12, n = seq & 4095;
        if (which == 0)      g_q[(b * NN + n) * HID + oo] = acc;
        else if (which == 1) g_kT[(b * HID + oo) * NN + n] = acc;
        else                 g_v[(b * NN + n) * HID + oo] = acc;
    }
}

// ---------------- Kernel 2: block-cooperative attention ----------------
// per-warp private histograms -> no cross-warp atomic conflicts
__shared__ unsigned sh_hist[8 * 256];
__shared__ ull      sh_crow[256];
__shared__ float    sh_q2[RPB * HID];
__shared__ float    sh_wred[8];
__shared__ float    sh_wctx[8][HID];
__shared__ float    sh_sctx[HID];
__shared__ unsigned sh_pref;
__shared__ int      sh_kneed;
__shared__ unsigned sh_cnt;
__shared__ float    sh_tot;

// warp0: pick radix bucket from summed 8-copy histogram; lane 0 updates smem state
__device__ __forceinline__ void select8(int lane) {
    unsigned pref = sh_pref;
    int kneed = sh_kneed;
    unsigned h8[8];
    int part = 0;
#pragma unroll
    for (int i = 0; i < 8; i++) {
        unsigned s = 0;
#pragma unroll
        for (int w2 = 0; w2 < 8; w2++) s += sh_hist[w2 * 256 + lane * 8 + i];
        h8[i] = s;
        part += (int)s;
    }
    int suff = part;
#pragma unroll
    for (int d2 = 1; d2 < 32; d2 <<= 1) {
        int v = __shfl_down_sync(FULL, suff, d2);
        if (lane + d2 < 32) suff += v;
    }
    int c = suff - part;
    unsigned bsel = 0; int krem = 0; bool found = false;
#pragma unroll
    for (int i = 7; i >= 0; i--) {
        int Cn = c;
        c += (int)h8[i];
        if (!found && c >= kneed && Cn < kneed) {
            bsel = (unsigned)(lane * 8 + i);
            krem = kneed - Cn;
            found = true;
        }
    }
    unsigned fm = __ballot_sync(FULL, found);
    int src = __ffs(fm) - 1;
    unsigned nb = __shfl_sync(FULL, bsel, src);
    int nk = __shfl_sync(FULL, krem, src);
    if (lane == 0) {
        sh_pref = (pref << 8) | nb;
        sh_kneed = nk;
    }
}

__global__ __launch_bounds__(256, 2) void attn_kernel(
    const float* __restrict__ wattn, const float* __restrict__ battn,
    const float* __restrict__ wmil, const float* __restrict__ bmil,
    float* __restrict__ out) {
    const int b = blockIdx.y;
    const int r0 = blockIdx.x * RPB;
    const int tid = threadIdx.x;
    const int lane = tid & 31;
    const int wid = tid >> 5;

    if (tid < RPB * HID) sh_q2[tid] = g_q[((size_t)b * NN + r0) * HID + tid];
    __syncthreads();

    // ---- Phase A: scores in registers; thread owns columns j = tid + 256*i ----
    unsigned u[RPB][16];
    {
        float acc[RPB][16];
#pragma unroll
        for (int r = 0; r < RPB; r++)
#pragma unroll
            for (int i = 0; i < 16; i++) acc[r][i] = 0.f;
        const float* kt = g_kT + (size_t)b * HID * NN;
#pragma unroll
        for (int d = 0; d < HID; d++) {
            float kv[16];
#pragma unroll
            for (int i = 0; i < 16; i++) kv[i] = kt[d * NN + tid + (i << 8)];
#pragma unroll
            for (int r = 0; r < RPB; r++) {
                float qv = sh_q2[r * HID + d];
#pragma unroll
                for (int i = 0; i < 16; i++) acc[r][i] = fmaf(qv, kv[i], acc[r][i]);
            }
        }
#pragma unroll
        for (int r = 0; r < RPB; r++)
#pragma unroll
            for (int i = 0; i < 16; i++) u[r][i] = orderf(acc[r][i]);
    }

    unsigned* hw = sh_hist + wid * 256;

    // ---- rows sequential; all 8 warps cooperate per row ----
    for (int r = 0; r < RPB; r++) {
        const int row = r0 + r;
        unsigned wk16[16];
#pragma unroll
        for (int i = 0; i < 16; i++) wk16[i] = u[r][i];

        // -- pass 0: top byte --
#pragma unroll
        for (int z = 0; z < 8; z++) sh_hist[z * 256 + tid] = 0u;
        if (tid == 0) { sh_pref = 0u; sh_kneed = KSEL; sh_cnt = 0u; }
        __syncthreads();
#pragma unroll
        for (int i = 0; i < 16; i++) atomicAdd(&hw[wk16[i] >> 24], 1u);
        __syncthreads();
        if (wid == 0) select8(lane);
        __syncthreads();
        const unsigned pref8 = sh_pref;

        // -- pass 1: byte 1 within selected bucket --
#pragma unroll
        for (int z = 0; z < 8; z++) sh_hist[z * 256 + tid] = 0u;
        __syncthreads();
#pragma unroll
        for (int i = 0; i < 16; i++) {
            unsigned uu = wk16[i];
            if ((uu >> 24) == pref8) atomicAdd(&hw[(uu >> 16) & 255u], 1u);
        }
        __syncthreads();
        if (wid == 0) select8(lane);
        __syncthreads();
        const unsigned pref16 = sh_pref;

        // -- compact candidates (u>>16 >= pref16), order irrelevant (sort canonicalizes) --
        sh_crow[tid] = 0ull;
        __syncthreads();
#pragma unroll
        for (int i = 0; i < 16; i++) {
            unsigned uu = wk16[i];
            bool p = (uu >> 16) >= pref16;
            unsigned mm = __ballot_sync(FULL, p);
            if (mm) {
                int leader = __ffs(mm) - 1;
                unsigned wbase = 0;
                if (lane == leader) wbase = atomicAdd(&sh_cnt, (unsigned)__popc(mm));
                wbase = __shfl_sync(FULL, wbase, leader);
                if (p) {
                    unsigned pos = wbase + __popc(mm & ((1u << lane) - 1u));
                    if (pos < 256u)
                        sh_crow[pos] = ((ull)uu << 32) |
                                       (ull)(~(unsigned)(tid + (i << 8)));
                }
            }
        }
        __syncthreads();

        if (sh_cnt > 256u) {
            // rare fallback: refine to exact 32-bit threshold (passes 2,3)
            for (int pp = 2; pp < 4; pp++) {
#pragma unroll
                for (int z = 0; z < 8; z++) sh_hist[z * 256 + tid] = 0u;
                __syncthreads();
                const unsigned prefc = sh_pref;
                const int shift = 24 - 8 * pp;
#pragma unroll
                for (int i = 0; i < 16; i++) {
                    unsigned uu = wk16[i];
                    if ((uu >> (shift + 8)) == prefc)
                        atomicAdd(&hw[(uu >> shift) & 255u], 1u);
                }
                __syncthreads();
                if (wid == 0) select8(lane);
                __syncthreads();
            }
            const unsigned T = sh_pref;
            if (tid == 0) sh_cnt = 0u;
            sh_crow[tid] = 0ull;
            __syncthreads();
#pragma unroll
            for (int i = 0; i < 16; i++) {
                unsigned uu = wk16[i];
                bool p = (uu >= T);
                unsigned mm = __ballot_sync(FULL, p);
                if (mm) {
                    int leader = __ffs(mm) - 1;
                    unsigned wbase = 0;
                    if (lane == leader) wbase = atomicAdd(&sh_cnt, (unsigned)__popc(mm));
                    wbase = __shfl_sync(FULL, wbase, leader);
                    if (p) {
                        unsigned pos = wbase + __popc(mm & ((1u << lane) - 1u));
                        if (pos < 256u)
                            sh_crow[pos] = ((ull)uu << 32) |
                                           (ull)(~(unsigned)(tid + (i << 8)));
                    }
                }
            }
            __syncthreads();
        }

        // -- hybrid bitonic sort, 256 elems, element index == tid, descending --
        ull mv = sh_crow[tid];
        for (int k2 = 2; k2 <= 256; k2 <<= 1) {
            bool up = ((tid & k2) == 0);
            for (int j = k2 >> 1; j > 0; j >>= 1) {
                ull other;
                if (j >= 32) {
                    sh_crow[tid] = mv;
                    __syncthreads();
                    other = sh_crow[tid ^ j];
                    __syncthreads();
                } else {
                    other = __shfl_xor_sync(FULL, mv, j);
                }
                bool lower = ((tid & j) == 0);
                bool takemax = (up == lower);
                ull mx = (mv > other) ? mv : other;
                ull mn = (mv > other) ? other : mv;
                mv = takemax ? mx : mn;
            }
        }
        sh_crow[tid] = mv;
        __syncthreads();

        // -- softmax over top-204 in exact lax.top_k order --
        const float smax = unorderf((unsigned)(sh_crow[0] >> 32)) * SCALE;
        const bool act = tid < KSEL;
        float e = 0.f;
        unsigned gidx = 0u;
        if (act) {
            float sv = unorderf((unsigned)(mv >> 32)) * SCALE;
            e = __expf(sv - smax);
            gidx = ~(unsigned)(mv & 0xffffffffull);
        }
        float s = e;
#pragma unroll
        for (int off = 16; off > 0; off >>= 1) s += __shfl_xor_sync(FULL, s, off);
        if (lane == 0) sh_wred[wid] = s;
        __syncthreads();
        if (tid == 0) {
            float t2 = 0.f;
#pragma unroll
            for (int w2 = 0; w2 < 8; w2++) t2 += sh_wred[w2];
            sh_tot = t2;
        }
        __syncthreads();

        float cd[HID];
#pragma unroll
        for (int d = 0; d < HID; d++) cd[d] = 0.f;
        if (act) {
            float p = e / sh_tot;
            out[8 + ((size_t)(b * NN + row)) * KSEL + tid] = p;
            const float2* vp = (const float2*)(g_v + ((size_t)b * NN + gidx) * HID);
            float2 a0 = vp[0], a1 = vp[1], a2 = vp[2], a3 = vp[3], a4 = vp[4];
            cd[0] = p * a0.x; cd[1] = p * a0.y;
            cd[2] = p * a1.x; cd[3] = p * a1.y;
            cd[4] = p * a2.x; cd[5] = p * a2.y;
            cd[6] = p * a3.x; cd[7] = p * a3.y;
            cd[8] = p * a4.x; cd[9] = p * a4.y;
        }
#pragma unroll
        for (int d = 0; d < HID; d++)
#pragma unroll
            for (int off = 16; off > 0; off >>= 1)
                cd[d] += __shfl_xor_sync(FULL, cd[d], off);
        if (lane == 0) {
#pragma unroll
            for (int d = 0; d < HID; d++) sh_wctx[wid][d] = cd[d];
        }
        __syncthreads();
        if (tid < HID) {
            float t3 = 0.f;
#pragma unroll
            for (int w2 = 0; w2 < 8; w2++) t3 += sh_wctx[w2][tid];
            sh_sctx[tid] = t3;
        }
        __syncthreads();
        if (wid == 0) {
            float sa = 0.f;
            if (lane < AFN) {
                sa = battn[lane];
#pragma unroll
                for (int d = 0; d < HID; d++) sa += sh_sctx[d] * wattn[lane * HID + d];
            }
            float t0 = (lane < AFN) ? sa * wmil[lane] : 0.f;
            float t1 = (lane < AFN) ? sa * wmil[AFN + lane] : 0.f;
#pragma unroll
            for (int off = 16; off > 0; off >>= 1) {
                t0 += __shfl_xor_sync(FULL, t0, off);
                t1 += __shfl_xor_sync(FULL, t1, off);
            }
            if (lane == 0) {
                g_logits[(b * NN + row) * 2 + 0] = t0 + bmil[0];
                g_logits[(b * NN + row) * 2 + 1] = t1 + bmil[1];
            }
        }
        __syncthreads();
    }
}

// ---------------- Kernel 3: deterministic pooled reduction (8 blocks) ----------------
__global__ __launch_bounds__(256) void pool_kernel(float* __restrict__ out) {
    __shared__ float wr[8];
    const int b = blockIdx.x >> 1, c = blockIdx.x & 1;
    const int tid = threadIdx.x, lane = tid & 31, w = tid >> 5;
    float acc = 0.f;
#pragma unroll
    for (int it = 0; it < NN / 256; it++)
        acc += g_logits[((size_t)b * NN + it * 256 + tid) * 2 + c];
#pragma unroll
    for (int off = 16; off > 0; off >>= 1) acc += __shfl_xor_sync(FULL, acc, off);
    if (lane == 0) wr[w] = acc;
    __syncthreads();
    if (tid == 0) {
        float t = 0.f;
#pragma unroll
        for (int i = 0; i < 8; i++) t += wr[i];
        out[b * 2 + c] = t * (1.0f / (float)NN);
    }
}

// ---------------- launcher ----------------
extern "C" void kernel_launch(void* const* d_in, const int* in_sizes, int n_in,
                              void* d_out, int out_size) {
    const float* x   = (const float*)d_in[0];
    const float* cw2 = (const float*)d_in[1];  const float* cb2 = (const float*)d_in[2];
    const float* cw3 = (const float*)d_in[3];  const float* cb3 = (const float*)d_in[4];
    const float* cw4 = (const float*)d_in[5];  const float* cb4 = (const float*)d_in[6];
    const float* cw5 = (const float*)d_in[7];  const float* cb5 = (const float*)d_in[8];
    const float* cw6 = (const float*)d_in[9];  const float* cb6 = (const float*)d_in[10];
    const float* cw7 = (const float*)d_in[11]; const float* cb7 = (const float*)d_in[12];
    const float* wq  = (const float*)d_in[13]; const float* bq  = (const float*)d_in[14];
    const float* wk  = (const float*)d_in[15]; const float* bk  = (const float*)d_in[16];
    const float* wv  = (const float*)d_in[17]; const float* bv  = (const float*)d_in[18];
    const float* wat = (const float*)d_in[19]; const float* bat = (const float*)d_in[20];
    const float* wm  = (const float*)d_in[21]; const float* bm  = (const float*)d_in[22];
    float* out = (float*)d_out;

    conv_qkv_kernel<<<(BB * NN) / 8, 256>>>(x, cw2, cb2, cw3, cb3, cw4, cb4,
                                            cw5, cb5, cw6, cb6, cw7, cb7,
                                            wq, bq, wk, bk, wv, bv);
    attn_kernel<<<dim3(NN / RPB, BB), 256>>>(wat, bat, wm, bm, out);
    pool_kernel<<<8, 256>>>(out);
}